// round 2
// baseline (speedup 1.0000x reference)
#include <cuda_runtime.h>
#include <cstdint>
#include <cstddef>

#define BATCH  64
#define TSTEPS 1000
#define NG     2
#define HH     160      // hidden per group (STEP)
#define DD     320      // CHANNEL*FEATURE / ... = G*HH
#define NGATE  640      // 4*HH
#define NCH    64
#define NF     5

// recurrence weight split: SK k-rows in smem, RK k-rows in registers
#define SK 88
#define RK 72
#define REC_SMEM (SK*NGATE*4 + HH*4 + NGATE*4)   // 225280 + 640 + 2560 = 228480 B

// ---------------- scratch (static device globals; no allocations) ----------------
__device__ float g_x1[(size_t)BATCH * TSTEPS * DD];            // stage-1 input  [row][d]
__device__ float g_x2[(size_t)BATCH * TSTEPS * DD];            // stage-2 input (permuted stage-1 output)
__device__ float g_gates[(size_t)BATCH * TSTEPS * NG * NGATE]; // x@Wih + b      [row][g][o]

// ---------------- transpose: [B,C,T,F] -> [B*T, C*F] ----------------
__global__ void transpose_kernel(const float* __restrict__ in)
{
    size_t idx = (size_t)blockIdx.x * blockDim.x + threadIdx.x;
    if (idx >= (size_t)BATCH * NCH * TSTEPS * NF) return;
    int f = (int)(idx % NF);
    size_t r = idx / NF;
    int t = (int)(r % TSTEPS); r /= TSTEPS;
    int c = (int)(r % NCH);    r /= NCH;
    int b = (int)r;
    g_x1[((size_t)(b * TSTEPS + t)) * DD + c * NF + f] = in[idx];
}

// ---------------- pre-GEMM: gates[row][g][o] = X[row, g*H : (g+1)*H] @ W[g] + bias[g] ----
// M = B*T = 64000, N = 640, K = 160.  Block tile 64x64, 256 threads, 4x4 per thread.
template <int STAGE>
__global__ __launch_bounds__(256) void pregemm_kernel(const float* __restrict__ W,
                                                      const float* __restrict__ bias)
{
    __shared__ float As[64][17];   // [m][k], padded to kill bank conflicts
    __shared__ float Bs[16][64];   // [k][n]

    const float* X = (STAGE == 1) ? g_x1 : g_x2;

    const int m0 = blockIdx.x * 64;
    const int n0 = blockIdx.y * 64;
    const int g  = blockIdx.z;
    const int tid = threadIdx.x;
    const int tm = tid >> 4;       // 0..15
    const int tn = tid & 15;       // 0..15

    const int aRow = tid >> 2;     // 0..63
    const int aK4  = tid & 3;      // 0..3  (float4 over k)
    const int bK   = tid >> 4;     // 0..15
    const int bN4  = tid & 15;     // 0..15 (float4 over n)

    const float* Xp = X + (size_t)m0 * DD + g * HH;
    const float* Wp = W + (size_t)g * HH * NGATE + n0;

    float acc[4][4];
#pragma unroll
    for (int i = 0; i < 4; i++)
#pragma unroll
        for (int j = 0; j < 4; j++) acc[i][j] = 0.f;

    for (int k0 = 0; k0 < HH; k0 += 16) {
        float4 av = *(const float4*)(Xp + (size_t)aRow * DD + k0 + aK4 * 4);
        As[aRow][aK4 * 4 + 0] = av.x;
        As[aRow][aK4 * 4 + 1] = av.y;
        As[aRow][aK4 * 4 + 2] = av.z;
        As[aRow][aK4 * 4 + 3] = av.w;
        float4 bv = *(const float4*)(Wp + (size_t)(k0 + bK) * NGATE + bN4 * 4);
        *(float4*)(&Bs[bK][bN4 * 4]) = bv;
        __syncthreads();
#pragma unroll
        for (int k = 0; k < 16; k++) {
            float a0 = As[tm * 4 + 0][k];
            float a1 = As[tm * 4 + 1][k];
            float a2 = As[tm * 4 + 2][k];
            float a3 = As[tm * 4 + 3][k];
            float4 b4 = *(const float4*)(&Bs[k][tn * 4]);
            acc[0][0] = fmaf(a0, b4.x, acc[0][0]);
            acc[0][1] = fmaf(a0, b4.y, acc[0][1]);
            acc[0][2] = fmaf(a0, b4.z, acc[0][2]);
            acc[0][3] = fmaf(a0, b4.w, acc[0][3]);
            acc[1][0] = fmaf(a1, b4.x, acc[1][0]);
            acc[1][1] = fmaf(a1, b4.y, acc[1][1]);
            acc[1][2] = fmaf(a1, b4.z, acc[1][2]);
            acc[1][3] = fmaf(a1, b4.w, acc[1][3]);
            acc[2][0] = fmaf(a2, b4.x, acc[2][0]);
            acc[2][1] = fmaf(a2, b4.y, acc[2][1]);
            acc[2][2] = fmaf(a2, b4.z, acc[2][2]);
            acc[2][3] = fmaf(a2, b4.w, acc[2][3]);
            acc[3][0] = fmaf(a3, b4.x, acc[3][0]);
            acc[3][1] = fmaf(a3, b4.y, acc[3][1]);
            acc[3][2] = fmaf(a3, b4.z, acc[3][2]);
            acc[3][3] = fmaf(a3, b4.w, acc[3][3]);
        }
        __syncthreads();
    }

    float4 bb = *(const float4*)(bias + g * NGATE + n0 + tn * 4);
#pragma unroll
    for (int i = 0; i < 4; i++) {
        int m = m0 + tm * 4 + i;
        float4 o;
        o.x = acc[i][0] + bb.x;
        o.y = acc[i][1] + bb.y;
        o.z = acc[i][2] + bb.z;
        o.w = acc[i][3] + bb.w;
        *(float4*)(g_gates + ((size_t)m * NG + g) * NGATE + n0 + tn * 4) = o;
    }
}

// ---------------- activations (overflow-safe, MUFU-based) ----------------
__device__ __forceinline__ float sigmoid_f(float x)
{
    return __fdividef(1.f, 1.f + __expf(-x));
}
__device__ __forceinline__ float tanh_f(float x)
{
    // 2/(1+e^{-2x}) - 1 : safe for x -> -inf (e -> inf -> result -1)
    return __fdividef(2.f, 1.f + __expf(-2.f * x)) - 1.f;
}

// ---------------- recurrence: 1 block per (batch, group) chain ----------------
// 640 threads, thread o owns gate column o.  Whh split: k<SK in smem, k>=SK in regs.
template <int STAGE>
__global__ __launch_bounds__(NGATE, 1) void rec_kernel(const float* __restrict__ Whh,
                                                       float* __restrict__ out)
{
    extern __shared__ float sm[];
    float4* w4      = (float4*)sm;               // [SK/4][NGATE]
    float*  h_sm    = sm + SK * NGATE;           // [HH]
    float*  act_sm  = h_sm + HH;                 // [NGATE]

    const int o = threadIdx.x;
    const int b = blockIdx.x >> 1;
    const int g = blockIdx.x & 1;

    const float* Wg = Whh + (size_t)g * HH * NGATE;

    // load smem part of weights (k = 0..SK-1), packed 4 k's per float4 per column
#pragma unroll 1
    for (int kk = 0; kk < SK / 4; kk++) {
        float4 v;
        v.x = Wg[(size_t)(4 * kk + 0) * NGATE + o];
        v.y = Wg[(size_t)(4 * kk + 1) * NGATE + o];
        v.z = Wg[(size_t)(4 * kk + 2) * NGATE + o];
        v.w = Wg[(size_t)(4 * kk + 3) * NGATE + o];
        w4[kk * NGATE + o] = v;
    }
    // register part (k = SK..159)
    float wreg[RK];
#pragma unroll
    for (int j = 0; j < RK; j++) wreg[j] = Wg[(size_t)(SK + j) * NGATE + o];

    float c = 0.f;
    if (o < HH) h_sm[o] = 0.f;
    __syncthreads();

    const float* grow = g_gates + ((size_t)b * TSTEPS * NG + g) * NGATE + o;
    float gx = grow[0];

    for (int t = 0; t < TSTEPS; t++) {
        float gx_next = (t + 1 < TSTEPS) ? __ldg(grow + (size_t)(t + 1) * NG * NGATE) : 0.f;

        float a0 = gx, a1 = 0.f, a2 = 0.f, a3 = 0.f;
        const float4* h4 = (const float4*)h_sm;
#pragma unroll
        for (int kk = 0; kk < SK / 4; kk++) {
            float4 w  = w4[kk * NGATE + o];
            float4 hv = h4[kk];
            a0 = fmaf(w.x, hv.x, a0);
            a1 = fmaf(w.y, hv.y, a1);
            a2 = fmaf(w.z, hv.z, a2);
            a3 = fmaf(w.w, hv.w, a3);
        }
#pragma unroll
        for (int jj = 0; jj < RK / 4; jj++) {
            float4 hv = h4[SK / 4 + jj];
            a0 = fmaf(wreg[4 * jj + 0], hv.x, a0);
            a1 = fmaf(wreg[4 * jj + 1], hv.y, a1);
            a2 = fmaf(wreg[4 * jj + 2], hv.z, a2);
            a3 = fmaf(wreg[4 * jj + 3], hv.w, a3);
        }
        float acc = (a0 + a1) + (a2 + a3);

        // i (0..159), f (160..319) -> sigmoid; g (320..479) -> tanh; o (480..639) -> sigmoid.
        // Boundaries are warp-aligned: no divergence.
        float a = (o < 2 * HH || o >= 3 * HH) ? sigmoid_f(acc) : tanh_f(acc);
        act_sm[o] = a;
        __syncthreads();

        if (o < HH) {
            float ia = act_sm[o];
            float fa = act_sm[HH + o];
            float ga = act_sm[2 * HH + o];
            float oa = act_sm[3 * HH + o];
            c = fmaf(fa, c, ia * ga);
            float hval = oa * tanh_f(c);
            h_sm[o] = hval;
            if (STAGE == 1) {
                // scatter into permuted stage-2 layout: d = g*160 + o ; j = (o/5)*10 + g*5 + (o%5)
                int i  = o / NF;
                int f  = o - i * NF;
                g_x2[((size_t)b * TSTEPS + t) * DD + i * 10 + g * NF + f] = hval;
            } else {
                // final output: out[b, c, t, f] with d = g*160 + o = c*5 + f
                int d  = g * HH + o;
                int cc = d / NF;
                int f  = d - cc * NF;
                out[(((size_t)b * NCH + cc) * TSTEPS + t) * NF + f] = hval;
            }
        }
        __syncthreads();
        gx = gx_next;
    }
}

// ---------------- launch ----------------
extern "C" void kernel_launch(void* const* d_in, const int* in_sizes, int n_in,
                              void* d_out, int out_size)
{
    (void)in_sizes; (void)n_in; (void)out_size;
    const float* input = (const float*)d_in[0];
    const float* Wih1  = (const float*)d_in[1];
    const float* Whh1  = (const float*)d_in[2];
    const float* b1    = (const float*)d_in[3];
    const float* Wih2  = (const float*)d_in[4];
    const float* Whh2  = (const float*)d_in[5];
    const float* b2    = (const float*)d_in[6];
    // d_in[7] = snd_index (permutation computed analytically in-kernel)
    float* out = (float*)d_out;

    cudaFuncSetAttribute(rec_kernel<1>, cudaFuncAttributeMaxDynamicSharedMemorySize, REC_SMEM);
    cudaFuncSetAttribute(rec_kernel<2>, cudaFuncAttributeMaxDynamicSharedMemorySize, REC_SMEM);

    const int n_in_elems = BATCH * NCH * TSTEPS * NF;
    transpose_kernel<<<(n_in_elems + 255) / 256, 256>>>(input);

    dim3 gg(BATCH * TSTEPS / 64, NGATE / 64, NG);
    pregemm_kernel<1><<<gg, 256>>>(Wih1, b1);
    rec_kernel<1><<<BATCH * NG, NGATE, REC_SMEM>>>(Whh1, nullptr);
    pregemm_kernel<2><<<gg, 256>>>(Wih2, b2);
    rec_kernel<2><<<BATCH * NG, NGATE, REC_SMEM>>>(Whh2, out);
}